// round 15
// baseline (speedup 1.0000x reference)
#include <cuda_runtime.h>
#include <cuda_fp16.h>
#include <cstdint>

// ---------------------------------------------------------------------------
// DeformableBlock R15: R14 + fp16 P buffer + launch split (GEMM = 4th launch).
//   k_prep: x -> padded NHWC fp16 (66x66).
//   k_prep_w: weight tiles (deform BK=64 + offset).
//   k_offconv16: offset conv via m16n8k16 + in-register bilinear precomp.
//   k_gemm_fused: balanced 148-CTA gather+GEMM + GN partials (P in fp16).
//   k_gn_finalize: stats reduce + normalize + ReLU + NCHW.
// ---------------------------------------------------------------------------

#define BATCH 4
#define CIN   256
#define COUT  256
#define HH    64
#define WW    64
#define HWSZ  4096
#define NPIX  16384
#define KT    9
#define KDIM  2304
#define OCOFF 18
#define GROUPS 32
#define CPG   8
#define NKB   72            // 32-wide K blocks (offset conv)
#define NKC   36            // 64-wide K chunks (deform GEMM)
#define PD    66
#define PHW   (PD*PD)
#define CPB   37            // GEMM CTAs per batch

__device__ __align__(16) __half g_xp [BATCH * PHW * CIN];   // padded NHWC fp16
__device__ __align__(16) __half g_wtB[NKC * 256 * 64];      // deform W [kc][o][k64]
__device__ __align__(16) __half g_wtO[NKB * 32 * 32];       // offset W tiles
__device__ int4   g_sidx[NPIX * KT];                        // padded corner idx
__device__ float4 g_sw  [NPIX * KT];
__device__ __align__(16) __half g_P [NPIX * COUT];          // pre-GN (fp16)
__device__ float2 g_gnp [BATCH * CPB * GROUPS];

static __device__ __forceinline__ uint32_t sptr(const void* p) {
    return (uint32_t)__cvta_generic_to_shared(p);
}
#define CP_ASYNC16(dst, src) \
    asm volatile("cp.async.cg.shared.global [%0], [%1], 16;\n" :: "r"(dst), "l"(src))
#define CP_COMMIT() asm volatile("cp.async.commit_group;\n")

#define LDMX4(r0, r1, r2, r3, addr)                                         \
    asm volatile("ldmatrix.sync.aligned.m8n8.x4.shared.b16 {%0,%1,%2,%3}, [%4];" \
                 : "=r"(r0), "=r"(r1), "=r"(r2), "=r"(r3) : "r"(addr))

#define MMA16816(d, a, b0, b1)                                              \
    asm volatile(                                                           \
        "mma.sync.aligned.m16n8k16.row.col.f32.f16.f16.f32 "                \
        "{%0,%1,%2,%3}, {%4,%5,%6,%7}, {%8,%9}, {%0,%1,%2,%3};\n"           \
        : "+f"((d)[0]), "+f"((d)[1]), "+f"((d)[2]), "+f"((d)[3])            \
        : "r"((a)[0]), "r"((a)[1]), "r"((a)[2]), "r"((a)[3]),               \
          "r"(b0), "r"(b1))

// ---------------------------------------------------------------------------
// K0: x transpose prep.  grid (128, 9, 4), 256 threads.
// ---------------------------------------------------------------------------
__global__ __launch_bounds__(256) void k_prep(const float* __restrict__ x) {
    __shared__ float tile[32][33];
    int role = blockIdx.y;
    int b = blockIdx.z;
    int t = threadIdx.x;

    if (role < 8) {
        int hw0 = blockIdx.x * 32, c0 = role * 32;
        int tx = t & 31, ty = t >> 5;
#pragma unroll
        for (int i = 0; i < 4; i++) {
            int c = c0 + ty + i * 8;
            tile[ty + i * 8][tx] = x[((long)b * CIN + c) * HWSZ + hw0 + tx];
        }
        __syncthreads();
#pragma unroll
        for (int i = 0; i < 4; i++) {
            int hw = hw0 + ty + i * 8;
            __half v = __float2half_rn(tile[tx][ty + i * 8]);
            int h = hw >> 6, w = hw & 63;
            g_xp[((size_t)b * PHW + (h + 1) * PD + (w + 1)) * CIN + c0 + tx] = v;
        }
    } else {
        uint32_t* xp32 = (uint32_t*)g_xp;
        for (int i = blockIdx.x * 256 + t; i < 260 * 128; i += 128 * 256) {
            int p = i >> 7, word = i & 127;
            int y, xx;
            if (p < 66)       { y = 0;        xx = p; }
            else if (p < 132) { y = 65;       xx = p - 66; }
            else if (p < 196) { y = p - 131;  xx = 0; }
            else              { y = p - 195;  xx = 65; }
            xp32[((size_t)b * PHW + y * PD + xx) * 128 + word] = 0u;
        }
    }
}

// ---------------------------------------------------------------------------
// K0b: weight prep (separate launch so GEMM lands 4th for ncu).
// ---------------------------------------------------------------------------
__global__ __launch_bounds__(256) void k_prep_w(const float* __restrict__ dw,
                                                const float* __restrict__ ow) {
    int t = threadIdx.x;
    if (blockIdx.y == 0) {
        for (int i = blockIdx.x * 256 + t; i < NKC * 16384; i += 160 * 256) {
            int kc = i >> 14, rem = i & 16383;
            int o = rem >> 6, ko = rem & 63;
            int tap = kc >> 2, c = (kc & 3) * 64 + ko;
            g_wtB[i] = __float2half_rn(dw[(o * CIN + c) * KT + tap]);
        }
    } else {
        for (int i = blockIdx.x * 256 + t; i < NKB * 1024; i += 160 * 256) {
            int kb = i >> 10, rem = i & 1023;
            int oc = rem >> 5, ko = rem & 31;
            int tap = kb >> 3, c = (kb & 7) * 32 + ko;
            g_wtO[i] = (oc < OCOFF)
                ? __float2half_rn(ow[(oc * CIN + c) * KT + tap])
                : __half(0.f);
        }
    }
}

// ---------------------------------------------------------------------------
// K1: offset conv via fp16 MMA + fused bilinear precomp.  grid=128, 256 thr.
// ---------------------------------------------------------------------------
__global__ __launch_bounds__(256) void k_offconv16(const float* __restrict__ ob) {
    __shared__ __align__(16) __half sA[3][128 * 40];
    __shared__ __align__(16) __half sB[3][32 * 40];
    uint32_t sbA = sptr(sA), sbB = sptr(sB);

    int t = threadIdx.x, lane = t & 31, wid = t >> 5;
    int m0 = blockIdx.x * 128;
    int r = t >> 1, seg = (t & 1) * 16;
    int pix0 = m0 + r;
    int b0 = pix0 >> 12, h0 = (pix0 >> 6) & 63, w0 = pix0 & 63;
    size_t basep = (size_t)b0 * PHW + h0 * PD + w0;
    int brow = t >> 2, bcol = (t & 3) * 8;

    float acc[4][4];
#pragma unroll
    for (int i = 0; i < 4; i++)
#pragma unroll
        for (int q = 0; q < 4; q++) acc[i][q] = 0.f;

#define OLOAD(stg, kb)                                                        \
    do {                                                                      \
        int tap = (kb) >> 3, cb = ((kb) & 7) * 32 + seg;                      \
        const __half* src =                                                   \
            g_xp + (basep + (tap / 3) * PD + (tap % 3)) * CIN + cb;           \
        CP_ASYNC16(sbA + (stg) * 10240 + (r * 40 + seg) * 2, src);            \
        CP_ASYNC16(sbA + (stg) * 10240 + (r * 40 + seg + 8) * 2, src + 8);    \
        if (t < 128)                                                          \
            CP_ASYNC16(sbB + (stg) * 2560 + (brow * 40 + bcol) * 2,           \
                       g_wtO + (kb) * 1024 + brow * 32 + bcol);               \
        CP_COMMIT();                                                          \
    } while (0)

    OLOAD(0, 0);
    OLOAD(1, 1);

    int lrow = lane & 15, lcol = (lane >> 4) * 8;
    for (int c = 0; c < NKB; c++) {
        int st = c % 3;
        if (c + 1 < NKB) {
            asm volatile("cp.async.wait_group 1;" ::: "memory");
        } else {
            asm volatile("cp.async.wait_group 0;" ::: "memory");
        }
        __syncthreads();
#pragma unroll
        for (int ks = 0; ks < 32; ks += 16) {
            int col = ks + lcol;
            uint32_t A0[4], t0, t1, t2, t3;
            LDMX4(A0[0], A0[1], A0[2], A0[3],
                  sbA + st * 10240 + ((wid * 16 + lrow) * 40 + col) * 2);
#pragma unroll
            for (int np = 0; np < 2; np++) {
                LDMX4(t0, t1, t2, t3,
                      sbB + st * 2560 + ((np * 16 + lrow) * 40 + col) * 2);
                MMA16816(acc[np * 2], A0, t0, t2);
                MMA16816(acc[np * 2 + 1], A0, t1, t3);
            }
        }
        if (c + 2 < NKB) OLOAD((c + 2) % 3, c + 2);
    }
#undef OLOAD

    // ---- fused bilinear precomp ----
    int rb = m0 + wid * 16 + (lane >> 2);
    int q = lane & 3;
#pragma unroll
    for (int nt = 0; nt < 3; nt++) {
        int tap = nt * 4 + q;
        if (tap < 9) {
            float by = ob[2 * tap], bx = ob[2 * tap + 1];
            int ky = tap / 3, kx = tap % 3;
#pragma unroll
            for (int rr = 0; rr < 2; rr++) {
                int pix = rb + rr * 8;
                float dy = acc[nt][rr * 2 + 0] + by;
                float dx = acc[nt][rr * 2 + 1] + bx;
                int h = (pix >> 6) & 63, w = pix & 63;
                float py = (float)(h - 1 + ky) + dy;
                float px = (float)(w - 1 + kx) + dx;
                float y0f = floorf(py), x0f = floorf(px);
                float ty = py - y0f, txf = px - x0f;
                int y0 = (int)y0f, x0 = (int)x0f;
                int y1 = y0 + 1, x1 = x0 + 1;
                float vy0 = (y0 >= 0 && y0 < HH) ? 1.f : 0.f;
                float vy1 = (y1 >= 0 && y1 < HH) ? 1.f : 0.f;
                float vx0 = (x0 >= 0 && x0 < WW) ? 1.f : 0.f;
                float vx1 = (x1 >= 0 && x1 < WW) ? 1.f : 0.f;
                int yc0 = min(max(y0, 0), HH - 1), yc1 = min(max(y1, 0), HH - 1);
                int xc0 = min(max(x0, 0), WW - 1), xc1 = min(max(x1, 0), WW - 1);
                g_sidx[pix * 9 + tap] = make_int4(
                    (yc0 + 1) * PD + xc0 + 1, (yc0 + 1) * PD + xc1 + 1,
                    (yc1 + 1) * PD + xc0 + 1, (yc1 + 1) * PD + xc1 + 1);
                g_sw[pix * 9 + tap] = make_float4(
                    (1.f - ty) * (1.f - txf) * vy0 * vx0,
                    (1.f - ty) * txf * vy0 * vx1,
                    ty * (1.f - txf) * vy1 * vx0,
                    ty * txf * vy1 * vx1);
            }
        }
    }
}

// ---------------------------------------------------------------------------
// K2: FUSED gather + fp16 GEMM + GN partials.  Balanced 148-CTA scheduler.
// ---------------------------------------------------------------------------
#define ASTRIDE 72
#define A_OFF(s)  ((s) * 16128)              // 112*72*2
#define B_OFF(s)  (32256 + (s) * 36864)      // 256*72*2
#define GEMM_SMEM (32256 + 2 * 36864)        // 105984

__global__ __launch_bounds__(512, 1) void k_gemm_fused() {
    extern __shared__ __align__(16) char smem[];
    uint32_t sb = sptr(smem);

    int bc = blockIdx.x;
    int bb = bc / CPB, cc = bc % CPB;
    int sbase   = (cc < 34) ? cc * 7 : 238 + (cc - 34) * 6;
    int nstrips = (cc < 34) ? 7 : 6;
    int nrows   = nstrips << 4;
    int m0 = bb * HWSZ + sbase * 16;

    int t = threadIdx.x, lane = t & 31, wid = t >> 5;
    int q = wid & 3, s0 = wid >> 2;
    bool has2 = (s0 + 4) < nstrips;
    int lrow = lane & 15, lcol = (lane >> 4) * 8;

    int r   = t >> 2;
    int s16 = (t & 3) * 16;
    bool gact = r < nrows;
    int pixg = m0 + r;
    const __half* xb = g_xp + (size_t)bb * PHW * CIN;

    float acc[2][8][4];
#pragma unroll
    for (int i = 0; i < 2; i++)
#pragma unroll
        for (int j = 0; j < 8; j++)
#pragma unroll
            for (int v = 0; v < 4; v++) acc[i][j][v] = 0.f;

    int4   I = make_int4(0, 0, 0, 0);
    float4 Wq = make_float4(0.f, 0.f, 0.f, 0.f);
    uint4  c0v, c1v, c2v, c3v;

#define GATHER_LDG(cn, half)                                                  \
    do {                                                                      \
        if ((half) == 0 && (((cn) & 3) == 0)) {                               \
            int tap = (cn) >> 2;                                              \
            I  = g_sidx[pixg * 9 + tap];                                      \
            Wq = g_sw[pixg * 9 + tap];                                        \
        }                                                                     \
        const __half* xc = xb + ((cn) & 3) * 64 + s16 + (half) * 8;           \
        c0v = *(const uint4*)(xc + (size_t)I.x * CIN);                        \
        c1v = *(const uint4*)(xc + (size_t)I.y * CIN);                        \
        c2v = *(const uint4*)(xc + (size_t)I.z * CIN);                        \
        c3v = *(const uint4*)(xc + (size_t)I.w * CIN);                        \
    } while (0)

#define GATHER_STORE(stg, half)                                               \
    do {                                                                      \
        const __half2* h0 = (const __half2*)&c0v;                             \
        const __half2* h1 = (const __half2*)&c1v;                             \
        const __half2* h2 = (const __half2*)&c2v;                             \
        const __half2* h3 = (const __half2*)&c3v;                             \
        __half2 outv[4];                                                      \
        _Pragma("unroll")                                                     \
        for (int j = 0; j < 4; j++) {                                         \
            float2 f0 = __half22float2(h0[j]);                                \
            float2 f1 = __half22float2(h1[j]);                                \
            float2 f2 = __half22float2(h2[j]);                                \
            float2 f3 = __half22float2(h3[j]);                                \
            float2 rr;                                                        \
            rr.x = Wq.x * f0.x + Wq.y * f1.x + Wq.z * f2.x + Wq.w * f3.x;     \
            rr.y = Wq.x * f0.y + Wq.y * f1.y + Wq.z * f2.y + Wq.w * f3.y;     \
            outv[j] = __float22half2_rn(rr);                                  \
        }                                                                     \
        *(uint4*)(smem + A_OFF(stg) + (r * ASTRIDE + s16 + (half) * 8) * 2) = \
            *(const uint4*)outv;                                              \
    } while (0)

#define LOAD_B(stg, kc)                                                       \
    do {                                                                      \
        const __half* bs = g_wtB + (size_t)(kc) * 16384                       \
                         + (t >> 1) * 64 + (t & 1) * 32;                      \
        uint32_t bd = sb + B_OFF(stg) + ((t >> 1) * ASTRIDE + (t & 1) * 32) * 2; \
        CP_ASYNC16(bd,      bs);                                              \
        CP_ASYNC16(bd + 16, bs + 8);                                          \
        CP_ASYNC16(bd + 32, bs + 16);                                         \
        CP_ASYNC16(bd + 48, bs + 24);                                         \
        CP_COMMIT();                                                          \
    } while (0)

    // prologue: stage 0
    if (gact) {
        GATHER_LDG(0, 0);  GATHER_STORE(0, 0);
        GATHER_LDG(0, 1);  GATHER_STORE(0, 1);
    }
    LOAD_B(0, 0);

    for (int ch = 0; ch < NKC; ch++) {
        int st = ch & 1;
        bool more = (ch + 1 < NKC);
        if (more && gact) GATHER_LDG(ch + 1, 0);
        asm volatile("cp.async.wait_group 0;" ::: "memory");
        __syncthreads();
        if (more) LOAD_B(st ^ 1, ch + 1);

        uint32_t Ab = sb + A_OFF(st);
        uint32_t Bb = sb + B_OFF(st);

#pragma unroll
        for (int gq = 0; gq < 4; gq++) {
            int col = gq * 16 + lcol;
            uint32_t A0[4], A1[4], Bf[4];
            LDMX4(A0[0], A0[1], A0[2], A0[3],
                  Ab + ((s0 * 16 + lrow) * ASTRIDE + col) * 2);
            if (has2)
                LDMX4(A1[0], A1[1], A1[2], A1[3],
                      Ab + (((s0 + 4) * 16 + lrow) * ASTRIDE + col) * 2);

            if (gq == 1 && more && gact) { GATHER_STORE(st ^ 1, 0); GATHER_LDG(ch + 1, 1); }
            if (gq == 3 && more && gact) { GATHER_STORE(st ^ 1, 1); }

#pragma unroll
            for (int np = 0; np < 4; np++) {
                LDMX4(Bf[0], Bf[1], Bf[2], Bf[3],
                      Bb + ((q * 64 + np * 16 + lrow) * ASTRIDE + col) * 2);
                MMA16816(acc[0][np * 2],     A0, Bf[0], Bf[2]);
                MMA16816(acc[0][np * 2 + 1], A0, Bf[1], Bf[3]);
                if (has2) {
                    MMA16816(acc[1][np * 2],     A1, Bf[0], Bf[2]);
                    MMA16816(acc[1][np * 2 + 1], A1, Bf[1], Bf[3]);
                }
            }
        }
    }
#undef GATHER_LDG
#undef GATHER_STORE
#undef LOAD_B

    // ---- write P (fp16) ----
    int nunits = has2 ? 2 : 1;
    for (int j = 0; j < nunits; j++) {
        int row = m0 + (s0 + j * 4) * 16 + (lane >> 2);
#pragma unroll
        for (int nt = 0; nt < 8; nt++) {
            int col = q * 64 + nt * 8 + (lane & 3) * 2;
            *(__half2*)&g_P[(size_t)row * COUT + col] =
                __floats2half2_rn(acc[j][nt][0], acc[j][nt][1]);
            *(__half2*)&g_P[(size_t)(row + 8) * COUT + col] =
                __floats2half2_rn(acc[j][nt][2], acc[j][nt][3]);
        }
    }

    // ---- GN partial sums (fp32, deterministic) ----
    __syncthreads();
    float* sgn = (float*)smem;
#pragma unroll
    for (int nt = 0; nt < 8; nt++) {
        float s = 0.f, ss = 0.f;
        for (int j = 0; j < nunits; j++)
#pragma unroll
            for (int v = 0; v < 4; v++) {
                float x = acc[j][nt][v];
                s += x;  ss += x * x;
            }
#pragma unroll
        for (int off = 16; off >= 1; off >>= 1) {
            s  += __shfl_xor_sync(0xffffffffu, s, off);
            ss += __shfl_xor_sync(0xffffffffu, ss, off);
        }
        if (lane == 0) {
            int g = q * 8 + nt;
            sgn[(g * 4 + s0) * 2 + 0] = s;
            sgn[(g * 4 + s0) * 2 + 1] = ss;
        }
    }
    __syncthreads();
    if (t < GROUPS) {
        float s = 0.f, ss = 0.f;
#pragma unroll
        for (int w = 0; w < 4; w++) {
            s  += sgn[(t * 4 + w) * 2 + 0];
            ss += sgn[(t * 4 + w) * 2 + 1];
        }
        g_gnp[bc * GROUPS + t] = make_float2(s, ss);
    }
}

// ---------------------------------------------------------------------------
// K3: finalize = stats reduce (37 partials) + normalize + ReLU + NCHW.
// ---------------------------------------------------------------------------
__global__ void k_gn_finalize(float* __restrict__ out,
                              const float* __restrict__ gamma,
                              const float* __restrict__ beta) {
    __shared__ float tile[32][33];
    __shared__ float sstat[4][2];
    int b = blockIdx.z, hw0 = blockIdx.x * 32, o0 = blockIdx.y * 32;
    int tx = threadIdx.x, ty = threadIdx.y;
    int t = ty * 32 + tx;

    if (t < 128) {
        int gl = t >> 5, blk = t & 31;
        int g = (o0 >> 3) + gl;
        float2 v = g_gnp[(b * CPB + blk) * GROUPS + g];
        float s = v.x, ss = v.y;
        if (blk < CPB - 32) {
            float2 v2 = g_gnp[(b * CPB + 32 + blk) * GROUPS + g];
            s += v2.x;  ss += v2.y;
        }
#pragma unroll
        for (int off = 16; off >= 1; off >>= 1) {
            s  += __shfl_xor_sync(0xffffffffu, s, off);
            ss += __shfl_xor_sync(0xffffffffu, ss, off);
        }
        if (blk == 0) {
            float inv = 1.f / (float)(CPG * HWSZ);
            float mean = s * inv;
            float var  = ss * inv - mean * mean;
            sstat[gl][0] = mean;
            sstat[gl][1] = rsqrtf(var + 1e-5f);
        }
    }
    __syncthreads();

    int o = o0 + tx;
    float mean = sstat[tx >> 3][0];
    float rstd = sstat[tx >> 3][1];
    float ga = gamma[o], be = beta[o];

#pragma unroll
    for (int i = 0; i < 4; i++) {
        int hw = hw0 + ty + i * 8;
        float v = __half2float(g_P[(size_t)(b * HWSZ + hw) * COUT + o]);
        v = (v - mean) * rstd * ga + be;
        tile[ty + i * 8][tx] = fmaxf(v, 0.f);
    }
    __syncthreads();
#pragma unroll
    for (int i = 0; i < 4; i++) {
        int oo = o0 + ty + i * 8;
        out[((long)b * COUT + oo) * HWSZ + hw0 + tx] = tile[tx][ty + i * 8];
    }
}

// ---------------------------------------------------------------------------
extern "C" void kernel_launch(void* const* d_in, const int* in_sizes, int n_in,
                              void* d_out, int out_size) {
    const float* x  = (const float*)d_in[0];
    const float* ow = (const float*)d_in[1];
    const float* ob = (const float*)d_in[2];
    const float* dw = (const float*)d_in[3];
    const float* ga = (const float*)d_in[4];
    const float* be = (const float*)d_in[5];
    float* out = (float*)d_out;

    cudaFuncSetAttribute(k_gemm_fused,
                         cudaFuncAttributeMaxDynamicSharedMemorySize, GEMM_SMEM);

    k_prep<<<dim3(128, 9, 4), 256>>>(x);                    // 1
    k_prep_w<<<dim3(160, 2), 256>>>(dw, ow);                // 2
    k_offconv16<<<128, 256>>>(ob);                          // 3
    k_gemm_fused<<<BATCH * CPB, 512, GEMM_SMEM>>>();        // 4  <- ncu target
    k_gn_finalize<<<dim3(HWSZ / 32, COUT / 32, BATCH), dim3(32, 8)>>>(out, ga, be);
}

// round 16
// speedup vs baseline: 1.0415x; 1.0415x over previous
#include <cuda_runtime.h>
#include <cuda_fp16.h>
#include <cstdint>

// ---------------------------------------------------------------------------
// DeformableBlock R16: high-occupancy fp16 GEMM — 1024 threads/CTA, 32 warps,
//   16x64 warp tiles (32 accumulator regs/thread), inline gather.
//   k_prep / k_prep_w / k_offconv16 / k_gemm_fused (4th launch) / k_gn_finalize.
// ---------------------------------------------------------------------------

#define BATCH 4
#define CIN   256
#define COUT  256
#define HH    64
#define WW    64
#define HWSZ  4096
#define NPIX  16384
#define KT    9
#define KDIM  2304
#define OCOFF 18
#define GROUPS 32
#define CPG   8
#define NKB   72            // 32-wide K blocks (offset conv)
#define NKC   36            // 64-wide K chunks (deform GEMM)
#define PD    66
#define PHW   (PD*PD)
#define CPB   37            // GEMM CTAs per batch

__device__ __align__(16) __half g_xp [BATCH * PHW * CIN];   // padded NHWC fp16
__device__ __align__(16) __half g_wtB[NKC * 256 * 64];      // deform W [kc][o][k64]
__device__ __align__(16) __half g_wtO[NKB * 32 * 32];       // offset W tiles
__device__ int4   g_sidx[NPIX * KT];                        // padded corner idx
__device__ float4 g_sw  [NPIX * KT];
__device__ __align__(16) __half g_P [NPIX * COUT];          // pre-GN (fp16)
__device__ float2 g_gnp [BATCH * CPB * GROUPS];

static __device__ __forceinline__ uint32_t sptr(const void* p) {
    return (uint32_t)__cvta_generic_to_shared(p);
}
#define CP_ASYNC16(dst, src) \
    asm volatile("cp.async.cg.shared.global [%0], [%1], 16;\n" :: "r"(dst), "l"(src))
#define CP_COMMIT() asm volatile("cp.async.commit_group;\n")

#define LDMX4(r0, r1, r2, r3, addr)                                         \
    asm volatile("ldmatrix.sync.aligned.m8n8.x4.shared.b16 {%0,%1,%2,%3}, [%4];" \
                 : "=r"(r0), "=r"(r1), "=r"(r2), "=r"(r3) : "r"(addr))

#define MMA16816(d, a, b0, b1)                                              \
    asm volatile(                                                           \
        "mma.sync.aligned.m16n8k16.row.col.f32.f16.f16.f32 "                \
        "{%0,%1,%2,%3}, {%4,%5,%6,%7}, {%8,%9}, {%0,%1,%2,%3};\n"           \
        : "+f"((d)[0]), "+f"((d)[1]), "+f"((d)[2]), "+f"((d)[3])            \
        : "r"((a)[0]), "r"((a)[1]), "r"((a)[2]), "r"((a)[3]),               \
          "r"(b0), "r"(b1))

// ---------------------------------------------------------------------------
// K0: x transpose prep.  grid (128, 9, 4), 256 threads.
// ---------------------------------------------------------------------------
__global__ __launch_bounds__(256) void k_prep(const float* __restrict__ x) {
    __shared__ float tile[32][33];
    int role = blockIdx.y;
    int b = blockIdx.z;
    int t = threadIdx.x;

    if (role < 8) {
        int hw0 = blockIdx.x * 32, c0 = role * 32;
        int tx = t & 31, ty = t >> 5;
#pragma unroll
        for (int i = 0; i < 4; i++) {
            int c = c0 + ty + i * 8;
            tile[ty + i * 8][tx] = x[((long)b * CIN + c) * HWSZ + hw0 + tx];
        }
        __syncthreads();
#pragma unroll
        for (int i = 0; i < 4; i++) {
            int hw = hw0 + ty + i * 8;
            __half v = __float2half_rn(tile[tx][ty + i * 8]);
            int h = hw >> 6, w = hw & 63;
            g_xp[((size_t)b * PHW + (h + 1) * PD + (w + 1)) * CIN + c0 + tx] = v;
        }
    } else {
        uint32_t* xp32 = (uint32_t*)g_xp;
        for (int i = blockIdx.x * 256 + t; i < 260 * 128; i += 128 * 256) {
            int p = i >> 7, word = i & 127;
            int y, xx;
            if (p < 66)       { y = 0;        xx = p; }
            else if (p < 132) { y = 65;       xx = p - 66; }
            else if (p < 196) { y = p - 131;  xx = 0; }
            else              { y = p - 195;  xx = 65; }
            xp32[((size_t)b * PHW + y * PD + xx) * 128 + word] = 0u;
        }
    }
}

// ---------------------------------------------------------------------------
// K0b: weight prep.
// ---------------------------------------------------------------------------
__global__ __launch_bounds__(256) void k_prep_w(const float* __restrict__ dw,
                                                const float* __restrict__ ow) {
    int t = threadIdx.x;
    if (blockIdx.y == 0) {
        for (int i = blockIdx.x * 256 + t; i < NKC * 16384; i += 160 * 256) {
            int kc = i >> 14, rem = i & 16383;
            int o = rem >> 6, ko = rem & 63;
            int tap = kc >> 2, c = (kc & 3) * 64 + ko;
            g_wtB[i] = __float2half_rn(dw[(o * CIN + c) * KT + tap]);
        }
    } else {
        for (int i = blockIdx.x * 256 + t; i < NKB * 1024; i += 160 * 256) {
            int kb = i >> 10, rem = i & 1023;
            int oc = rem >> 5, ko = rem & 31;
            int tap = kb >> 3, c = (kb & 7) * 32 + ko;
            g_wtO[i] = (oc < OCOFF)
                ? __float2half_rn(ow[(oc * CIN + c) * KT + tap])
                : __half(0.f);
        }
    }
}

// ---------------------------------------------------------------------------
// K1: offset conv via fp16 MMA + fused bilinear precomp.  grid=128, 256 thr.
// ---------------------------------------------------------------------------
__global__ __launch_bounds__(256) void k_offconv16(const float* __restrict__ ob) {
    __shared__ __align__(16) __half sA[3][128 * 40];
    __shared__ __align__(16) __half sB[3][32 * 40];
    uint32_t sbA = sptr(sA), sbB = sptr(sB);

    int t = threadIdx.x, lane = t & 31, wid = t >> 5;
    int m0 = blockIdx.x * 128;
    int r = t >> 1, seg = (t & 1) * 16;
    int pix0 = m0 + r;
    int b0 = pix0 >> 12, h0 = (pix0 >> 6) & 63, w0 = pix0 & 63;
    size_t basep = (size_t)b0 * PHW + h0 * PD + w0;
    int brow = t >> 2, bcol = (t & 3) * 8;

    float acc[4][4];
#pragma unroll
    for (int i = 0; i < 4; i++)
#pragma unroll
        for (int q = 0; q < 4; q++) acc[i][q] = 0.f;

#define OLOAD(stg, kb)                                                        \
    do {                                                                      \
        int tap = (kb) >> 3, cb = ((kb) & 7) * 32 + seg;                      \
        const __half* src =                                                   \
            g_xp + (basep + (tap / 3) * PD + (tap % 3)) * CIN + cb;           \
        CP_ASYNC16(sbA + (stg) * 10240 + (r * 40 + seg) * 2, src);            \
        CP_ASYNC16(sbA + (stg) * 10240 + (r * 40 + seg + 8) * 2, src + 8);    \
        if (t < 128)                                                          \
            CP_ASYNC16(sbB + (stg) * 2560 + (brow * 40 + bcol) * 2,           \
                       g_wtO + (kb) * 1024 + brow * 32 + bcol);               \
        CP_COMMIT();                                                          \
    } while (0)

    OLOAD(0, 0);
    OLOAD(1, 1);

    int lrow = lane & 15, lcol = (lane >> 4) * 8;
    for (int c = 0; c < NKB; c++) {
        int st = c % 3;
        if (c + 1 < NKB) {
            asm volatile("cp.async.wait_group 1;" ::: "memory");
        } else {
            asm volatile("cp.async.wait_group 0;" ::: "memory");
        }
        __syncthreads();
#pragma unroll
        for (int ks = 0; ks < 32; ks += 16) {
            int col = ks + lcol;
            uint32_t A0[4], t0, t1, t2, t3;
            LDMX4(A0[0], A0[1], A0[2], A0[3],
                  sbA + st * 10240 + ((wid * 16 + lrow) * 40 + col) * 2);
#pragma unroll
            for (int np = 0; np < 2; np++) {
                LDMX4(t0, t1, t2, t3,
                      sbB + st * 2560 + ((np * 16 + lrow) * 40 + col) * 2);
                MMA16816(acc[np * 2], A0, t0, t2);
                MMA16816(acc[np * 2 + 1], A0, t1, t3);
            }
        }
        if (c + 2 < NKB) OLOAD((c + 2) % 3, c + 2);
    }
#undef OLOAD

    // ---- fused bilinear precomp ----
    int rb = m0 + wid * 16 + (lane >> 2);
    int q = lane & 3;
#pragma unroll
    for (int nt = 0; nt < 3; nt++) {
        int tap = nt * 4 + q;
        if (tap < 9) {
            float by = ob[2 * tap], bx = ob[2 * tap + 1];
            int ky = tap / 3, kx = tap % 3;
#pragma unroll
            for (int rr = 0; rr < 2; rr++) {
                int pix = rb + rr * 8;
                float dy = acc[nt][rr * 2 + 0] + by;
                float dx = acc[nt][rr * 2 + 1] + bx;
                int h = (pix >> 6) & 63, w = pix & 63;
                float py = (float)(h - 1 + ky) + dy;
                float px = (float)(w - 1 + kx) + dx;
                float y0f = floorf(py), x0f = floorf(px);
                float ty = py - y0f, txf = px - x0f;
                int y0 = (int)y0f, x0 = (int)x0f;
                int y1 = y0 + 1, x1 = x0 + 1;
                float vy0 = (y0 >= 0 && y0 < HH) ? 1.f : 0.f;
                float vy1 = (y1 >= 0 && y1 < HH) ? 1.f : 0.f;
                float vx0 = (x0 >= 0 && x0 < WW) ? 1.f : 0.f;
                float vx1 = (x1 >= 0 && x1 < WW) ? 1.f : 0.f;
                int yc0 = min(max(y0, 0), HH - 1), yc1 = min(max(y1, 0), HH - 1);
                int xc0 = min(max(x0, 0), WW - 1), xc1 = min(max(x1, 0), WW - 1);
                g_sidx[pix * 9 + tap] = make_int4(
                    (yc0 + 1) * PD + xc0 + 1, (yc0 + 1) * PD + xc1 + 1,
                    (yc1 + 1) * PD + xc0 + 1, (yc1 + 1) * PD + xc1 + 1);
                g_sw[pix * 9 + tap] = make_float4(
                    (1.f - ty) * (1.f - txf) * vy0 * vx0,
                    (1.f - ty) * txf * vy0 * vx1,
                    ty * (1.f - txf) * vy1 * vx0,
                    ty * txf * vy1 * vx1);
            }
        }
    }
}

// ---------------------------------------------------------------------------
// K2: high-occupancy fused gather + fp16 GEMM + GN partials.
//   148 CTAs (strip scheduler), 1024 thr = 32 warps, 16x64 warp tiles.
//   BK=64, 2-stage, inline gather (no persistent staging regs).
// ---------------------------------------------------------------------------
#define ASTRIDE 72
#define A_OFF(s)  ((s) * 16128)              // 112*72*2
#define B_OFF(s)  (32256 + (s) * 36864)      // 256*72*2
#define GEMM_SMEM (32256 + 2 * 36864)        // 105984

__global__ __launch_bounds__(1024, 1) void k_gemm_fused() {
    extern __shared__ __align__(16) char smem[];
    uint32_t sb = sptr(smem);

    int bc = blockIdx.x;
    int bb = bc / CPB, cc = bc % CPB;
    int sbase   = (cc < 34) ? cc * 7 : 238 + (cc - 34) * 6;
    int nstrips = (cc < 34) ? 7 : 6;
    int nrows   = nstrips << 4;
    int m0 = bb * HWSZ + sbase * 16;

    int t = threadIdx.x, lane = t & 31, wid = t >> 5;
    int q = wid & 3, s = wid >> 2;          // q: 64-col quarter, s: strip slot
    bool wact = s < nstrips;
    int lrow = lane & 15, lcol = (lane >> 4) * 8;

    int r  = t >> 3;                        // gather: 1 row, 8 channels
    int s8 = (t & 7) * 8;
    bool gact = r < nrows;
    int pixg = m0 + r;
    const __half* xb = g_xp + (size_t)bb * PHW * CIN;

    float acc[8][4];
#pragma unroll
    for (int j = 0; j < 8; j++)
#pragma unroll
        for (int v = 0; v < 4; v++) acc[j][v] = 0.f;

#define GATHER(stg, cn)                                                       \
    do {                                                                      \
        int tap = (cn) >> 2;                                                  \
        int4   I  = g_sidx[pixg * 9 + tap];                                   \
        float4 Wq = g_sw[pixg * 9 + tap];                                     \
        const __half* xc = xb + ((cn) & 3) * 64 + s8;                         \
        uint4 c0v = *(const uint4*)(xc + (size_t)I.x * CIN);                  \
        uint4 c1v = *(const uint4*)(xc + (size_t)I.y * CIN);                  \
        uint4 c2v = *(const uint4*)(xc + (size_t)I.z * CIN);                  \
        uint4 c3v = *(const uint4*)(xc + (size_t)I.w * CIN);                  \
        const __half2* h0 = (const __half2*)&c0v;                             \
        const __half2* h1 = (const __half2*)&c1v;                             \
        const __half2* h2 = (const __half2*)&c2v;                             \
        const __half2* h3 = (const __half2*)&c3v;                             \
        __half2 outv[4];                                                      \
        _Pragma("unroll")                                                     \
        for (int j = 0; j < 4; j++) {                                         \
            float2 f0 = __half22float2(h0[j]);                                \
            float2 f1 = __half22float2(h1[j]);                                \
            float2 f2 = __half22float2(h2[j]);                                \
            float2 f3 = __half22float2(h3[j]);                                \
            float2 rr;                                                        \
            rr.x = Wq.x * f0.x + Wq.y * f1.x + Wq.z * f2.x + Wq.w * f3.x;     \
            rr.y = Wq.x * f0.y + Wq.y * f1.y + Wq.z * f2.y + Wq.w * f3.y;     \
            outv[j] = __float22half2_rn(rr);                                  \
        }                                                                     \
        *(uint4*)(smem + A_OFF(stg) + (r * ASTRIDE + s8) * 2) =               \
            *(const uint4*)outv;                                              \
    } while (0)

#define LOAD_B(stg, kc)                                                       \
    do {                                                                      \
        const __half* bs = g_wtB + (size_t)(kc) * 16384                       \
                         + (t >> 2) * 64 + (t & 3) * 16;                      \
        uint32_t bd = sb + B_OFF(stg) + ((t >> 2) * ASTRIDE + (t & 3) * 16) * 2; \
        CP_ASYNC16(bd,      bs);                                              \
        CP_ASYNC16(bd + 16, bs + 8);                                          \
        CP_COMMIT();                                                          \
    } while (0)

    // prologue
    if (gact) GATHER(0, 0);
    LOAD_B(0, 0);

    for (int ch = 0; ch < NKC; ch++) {
        int st = ch & 1;
        bool more = (ch + 1 < NKC);
        asm volatile("cp.async.wait_group 0;" ::: "memory");
        __syncthreads();
        if (more) LOAD_B(st ^ 1, ch + 1);

        uint32_t Ab = sb + A_OFF(st) + ((s * 16 + lrow) * ASTRIDE) * 2;
        uint32_t Bb = sb + B_OFF(st) + ((q * 64 + lrow) * ASTRIDE) * 2;

        if (wact) {
#pragma unroll
            for (int ks = 0; ks < 64; ks += 16) {
                int col2 = (ks + lcol) * 2;
                uint32_t Af[4], Bf[4];
                LDMX4(Af[0], Af[1], Af[2], Af[3], Ab + col2);
#pragma unroll
                for (int np = 0; np < 4; np++) {
                    LDMX4(Bf[0], Bf[1], Bf[2], Bf[3],
                          Bb + (np * 16 * ASTRIDE) * 2 + col2);
                    MMA16816(acc[np * 2],     Af, Bf[0], Bf[2]);
                    MMA16816(acc[np * 2 + 1], Af, Bf[1], Bf[3]);
                }
            }
        }
        if (more && gact) GATHER(st ^ 1, ch + 1);
    }
#undef GATHER
#undef LOAD_B

    // ---- write P (fp16) ----
    if (wact) {
        int row = m0 + s * 16 + (lane >> 2);
#pragma unroll
        for (int nt = 0; nt < 8; nt++) {
            int col = q * 64 + nt * 8 + (lane & 3) * 2;
            *(__half2*)&g_P[(size_t)row * COUT + col] =
                __floats2half2_rn(acc[nt][0], acc[nt][1]);
            *(__half2*)&g_P[(size_t)(row + 8) * COUT + col] =
                __floats2half2_rn(acc[nt][2], acc[nt][3]);
        }
    }

    // ---- GN partial sums (fp32, deterministic) ----
    __syncthreads();
    float* sgn = (float*)smem;              // [32 groups][8 slots][2]
#pragma unroll
    for (int nt = 0; nt < 8; nt++) {
        float sv = 0.f, ssv = 0.f;
#pragma unroll
        for (int v = 0; v < 4; v++) {
            float x = acc[nt][v];
            sv += x;  ssv += x * x;
        }
#pragma unroll
        for (int off = 16; off >= 1; off >>= 1) {
            sv  += __shfl_xor_sync(0xffffffffu, sv, off);
            ssv += __shfl_xor_sync(0xffffffffu, ssv, off);
        }
        if (lane == 0) {
            int g = q * 8 + nt;
            sgn[(g * 8 + s) * 2 + 0] = sv;
            sgn[(g * 8 + s) * 2 + 1] = ssv;
        }
    }
    __syncthreads();
    if (t < GROUPS) {
        float sv = 0.f, ssv = 0.f;
#pragma unroll
        for (int w = 0; w < 8; w++) {
            sv  += sgn[(t * 8 + w) * 2 + 0];
            ssv += sgn[(t * 8 + w) * 2 + 1];
        }
        g_gnp[bc * GROUPS + t] = make_float2(sv, ssv);
    }
}

// ---------------------------------------------------------------------------
// K3: finalize = stats reduce (37 partials) + normalize + ReLU + NCHW.
// ---------------------------------------------------------------------------
__global__ void k_gn_finalize(float* __restrict__ out,
                              const float* __restrict__ gamma,
                              const float* __restrict__ beta) {
    __shared__ float tile[32][33];
    __shared__ float sstat[4][2];
    int b = blockIdx.z, hw0 = blockIdx.x * 32, o0 = blockIdx.y * 32;
    int tx = threadIdx.x, ty = threadIdx.y;
    int t = ty * 32 + tx;

    if (t < 128) {
        int gl = t >> 5, blk = t & 31;
        int g = (o0 >> 3) + gl;
        float2 v = g_gnp[(b * CPB + blk) * GROUPS + g];
        float s = v.x, ss = v.y;
        if (blk < CPB - 32) {
            float2 v2 = g_gnp[(b * CPB + 32 + blk) * GROUPS + g];
            s += v2.x;  ss += v2.y;
        }
#pragma unroll
        for (int off = 16; off >= 1; off >>= 1) {
            s  += __shfl_xor_sync(0xffffffffu, s, off);
            ss += __shfl_xor_sync(0xffffffffu, ss, off);
        }
        if (blk == 0) {
            float inv = 1.f / (float)(CPG * HWSZ);
            float mean = s * inv;
            float var  = ss * inv - mean * mean;
            sstat[gl][0] = mean;
            sstat[gl][1] = rsqrtf(var + 1e-5f);
        }
    }
    __syncthreads();

    int o = o0 + tx;
    float mean = sstat[tx >> 3][0];
    float rstd = sstat[tx >> 3][1];
    float ga = gamma[o], be = beta[o];

#pragma unroll
    for (int i = 0; i < 4; i++) {
        int hw = hw0 + ty + i * 8;
        float v = __half2float(g_P[(size_t)(b * HWSZ + hw) * COUT + o]);
        v = (v - mean) * rstd * ga + be;
        tile[ty + i * 8][tx] = fmaxf(v, 0.f);
    }
    __syncthreads();
#pragma unroll
    for (int i = 0; i < 4; i++) {
        int oo = o0 + ty + i * 8;
        out[((long)b * COUT + oo) * HWSZ + hw0 + tx] = tile[tx][ty + i * 8];
    }
}

// ---------------------------------------------------------------------------
extern "C" void kernel_launch(void* const* d_in, const int* in_sizes, int n_in,
                              void* d_out, int out_size) {
    const float* x  = (const float*)d_in[0];
    const float* ow = (const float*)d_in[1];
    const float* ob = (const float*)d_in[2];
    const float* dw = (const float*)d_in[3];
    const float* ga = (const float*)d_in[4];
    const float* be = (const float*)d_in[5];
    float* out = (float*)d_out;

    cudaFuncSetAttribute(k_gemm_fused,
                         cudaFuncAttributeMaxDynamicSharedMemorySize, GEMM_SMEM);

    k_prep<<<dim3(128, 9, 4), 256>>>(x);                    // 1
    k_prep_w<<<dim3(160, 2), 256>>>(dw, ow);                // 2
    k_offconv16<<<128, 256>>>(ob);                          // 3
    k_gemm_fused<<<BATCH * CPB, 1024, GEMM_SMEM>>>();       // 4  <- ncu target
    k_gn_finalize<<<dim3(HWSZ / 32, COUT / 32, BATCH), dim3(32, 8)>>>(out, ga, be);
}